// round 1
// baseline (speedup 1.0000x reference)
#include <cuda_runtime.h>

// Inverse 2D DWT, single level.
// Inputs (metadata order): ss, sd, ds, dd : (B,C,H,W) f32 ; h, g : (6,) f32
// Output: (B,C,2H,2W) f32
//
// Polyphase: fh0=[h4,h2,h0], fh1=[h5,h3,h1]; same for g. Reflect pad 1.
// out(2r+py, 2c+px) = sum_j fh[px][j]*sv_py(r, c-1+j) + fg[px][j]*dv_py(r, c-1+j)
// sv_py(r,w) = sum_i fh[py][i]*ss[refl(r-1+i)][w] + fg[py][i]*sd[refl(r-1+i)][w]
// dv_py      = same with ds/dd.

#define BB 4
#define CC 64
#define HH 256
#define WW 256
#define TH 8
#define TW 64
#define NTHREADS 256

__device__ __forceinline__ int reflH(int i) {
    return i < 0 ? -i : (i >= HH ? 2 * HH - 2 - i : i);
}
__device__ __forceinline__ int reflW(int i) {
    return i < 0 ? -i : (i >= WW ? 2 * WW - 2 - i : i);
}

__global__ __launch_bounds__(NTHREADS)
void idwt2d_kernel(const float* __restrict__ ss, const float* __restrict__ sd,
                   const float* __restrict__ ds, const float* __restrict__ dd,
                   const float* __restrict__ hf, const float* __restrict__ gf,
                   float* __restrict__ out) {
    // smem column-pass tile: {sv0, sv1, dv0, dv1} per (row, col)
    __shared__ float4 smem[TH][TW + 2];

    const int t = threadIdx.x;
    const int bc = blockIdx.z;
    const int rbase = blockIdx.y * TH;
    const int cbase = blockIdx.x * TW;

    const size_t ofs = (size_t)bc * (HH * WW);
    const float* __restrict__ pss = ss + ofs;
    const float* __restrict__ psd = sd + ofs;
    const float* __restrict__ pds = ds + ofs;
    const float* __restrict__ pdd = dd + ofs;

    const float h0 = __ldg(hf + 0), h1 = __ldg(hf + 1), h2 = __ldg(hf + 2);
    const float h3 = __ldg(hf + 3), h4 = __ldg(hf + 4), h5 = __ldg(hf + 5);
    const float g0 = __ldg(gf + 0), g1 = __ldg(gf + 1), g2 = __ldg(gf + 2);
    const float g3 = __ldg(gf + 3), g4 = __ldg(gf + 4), g5 = __ldg(gf + 5);

    // ---- Stage 1: column (H) pass into smem ----
    #pragma unroll
    for (int idx = t; idx < TH * (TW + 2); idx += NTHREADS) {
        const int lr = idx / (TW + 2);
        const int lc = idx - lr * (TW + 2);
        const int r = rbase + lr;
        const int w = reflW(cbase - 1 + lc);
        const int rm = reflH(r - 1);
        const int rp = reflH(r + 1);

        const float s0 = pss[(size_t)rm * WW + w];
        const float s1 = pss[(size_t)r  * WW + w];
        const float s2 = pss[(size_t)rp * WW + w];
        const float t0 = psd[(size_t)rm * WW + w];
        const float t1 = psd[(size_t)r  * WW + w];
        const float t2 = psd[(size_t)rp * WW + w];
        const float u0 = pds[(size_t)rm * WW + w];
        const float u1 = pds[(size_t)r  * WW + w];
        const float u2 = pds[(size_t)rp * WW + w];
        const float v0 = pdd[(size_t)rm * WW + w];
        const float v1 = pdd[(size_t)r  * WW + w];
        const float v2 = pdd[(size_t)rp * WW + w];

        float4 sv;
        sv.x = h4 * s0 + h2 * s1 + h0 * s2 + g4 * t0 + g2 * t1 + g0 * t2;  // sv0
        sv.y = h5 * s0 + h3 * s1 + h1 * s2 + g5 * t0 + g3 * t1 + g1 * t2;  // sv1
        sv.z = h4 * u0 + h2 * u1 + h0 * u2 + g4 * v0 + g2 * v1 + g0 * v2;  // dv0
        sv.w = h5 * u0 + h3 * u1 + h1 * u2 + g5 * v0 + g3 * v1 + g1 * v2;  // dv1
        smem[lr][lc] = sv;
    }

    __syncthreads();

    // ---- Stage 2: row (W) pass, write 2x2 output per input position ----
    float* __restrict__ pout = out + (size_t)bc * (4 * HH * WW);  // (2H, 2W)

    #pragma unroll
    for (int idx = t; idx < TH * TW; idx += NTHREADS) {
        const int lr = idx >> 6;   // / TW
        const int lc = idx & 63;   // % TW
        const float4 a = smem[lr][lc];       // col c-1
        const float4 b = smem[lr][lc + 1];   // col c
        const float4 c = smem[lr][lc + 2];   // col c+1

        const float o00 = h4 * a.x + h2 * b.x + h0 * c.x + g4 * a.z + g2 * b.z + g0 * c.z;
        const float o01 = h5 * a.x + h3 * b.x + h1 * c.x + g5 * a.z + g3 * b.z + g1 * c.z;
        const float o10 = h4 * a.y + h2 * b.y + h0 * c.y + g4 * a.w + g2 * b.w + g0 * c.w;
        const float o11 = h5 * a.y + h3 * b.y + h1 * c.y + g5 * a.w + g3 * b.w + g1 * c.w;

        const int r = rbase + lr;
        const int cidx = cbase + lc;
        float2* row0 = reinterpret_cast<float2*>(pout + (size_t)(2 * r)     * (2 * WW) + 2 * cidx);
        float2* row1 = reinterpret_cast<float2*>(pout + (size_t)(2 * r + 1) * (2 * WW) + 2 * cidx);
        *row0 = make_float2(o00, o01);
        *row1 = make_float2(o10, o11);
    }
}

extern "C" void kernel_launch(void* const* d_in, const int* in_sizes, int n_in,
                              void* d_out, int out_size) {
    const float* ss = (const float*)d_in[0];
    const float* sd = (const float*)d_in[1];
    const float* ds = (const float*)d_in[2];
    const float* dd = (const float*)d_in[3];
    const float* h  = (const float*)d_in[4];
    const float* g  = (const float*)d_in[5];
    float* out = (float*)d_out;

    dim3 grid(WW / TW, HH / TH, BB * CC);   // (4, 32, 256)
    dim3 block(NTHREADS);
    idwt2d_kernel<<<grid, block>>>(ss, sd, ds, dd, h, g, out);
}

// round 2
// speedup vs baseline: 1.2079x; 1.2079x over previous
#include <cuda_runtime.h>

// Inverse 2D DWT, single level. (B,C,H,W)=(4,64,256,256) f32 -> (B,C,512,512) f32.
// Strategy: one block per (b*c, 32-row chunk), full W strip.
//  - Column pass: rolling 3-row register window, each input row loaded once
//    (LDG.64 pairs, prefetched one iteration ahead). Results (sv0,sv1,dv0,dv1)
//    per column go to double-buffered smem rows.
//  - Row pass: 3-tap horizontal filter over smem, outputs interleaved and
//    written as float4 (16B) stores.
//  - All FMAs are packed fp32x2 (FFMA2) across adjacent columns; filter
//    coefficients dup-packed once per thread.

#define HH 256
#define WW 256
#define ROWS 32
#define NT 128            // threads = WW/2, each thread owns 2 adjacent columns

typedef unsigned long long u64;

__device__ __forceinline__ u64 pk(float lo, float hi) {
    u64 r; asm("mov.b64 %0, {%1, %2};" : "=l"(r) : "f"(lo), "f"(hi)); return r;
}
__device__ __forceinline__ void unpk(u64 v, float& lo, float& hi) {
    asm("mov.b64 {%0, %1}, %2;" : "=f"(lo), "=f"(hi) : "l"(v));
}
__device__ __forceinline__ u64 ffma2(u64 a, u64 b, u64 c) {
    u64 d; asm("fma.rn.f32x2 %0, %1, %2, %3;" : "=l"(d) : "l"(a), "l"(b), "l"(c)); return d;
}
__device__ __forceinline__ u64 fmul2(u64 a, u64 b) {
    u64 d; asm("mul.rn.f32x2 %0, %1, %2;" : "=l"(d) : "l"(a), "l"(b)); return d;
}

__device__ __forceinline__ int reflH(int i) {
    return i < 0 ? -i : (i >= HH ? 2 * HH - 2 - i : i);
}

__device__ __forceinline__ u64 ldg2(const float* __restrict__ p, int row) {
    return *(const u64*)(p + (size_t)row * WW);
}

__global__ __launch_bounds__(NT)
void idwt2d(const float* __restrict__ ss, const float* __restrict__ sd,
            const float* __restrict__ ds, const float* __restrict__ dd,
            const float* __restrict__ hf, const float* __restrict__ gf,
            float* __restrict__ out)
{
    // [buf][array: sv0,sv1,dv0,dv1][2 lead halo + WW + tail pad]
    __shared__ float sm[2][4][WW + 8];

    const int tx = threadIdx.x;
    const int bc = blockIdx.z;
    const int r0 = blockIdx.y * ROWS;
    const int c  = 2 * tx;                 // first of this thread's 2 columns

    const size_t inofs = (size_t)bc * (HH * WW) + c;
    const float* __restrict__ pss = ss + inofs;
    const float* __restrict__ psd = sd + inofs;
    const float* __restrict__ pds = ds + inofs;
    const float* __restrict__ pdd = dd + inofs;
    float* __restrict__ pout = out + (size_t)bc * (4 * HH * WW) + 2 * c;

    // dup-packed filter coefficients (f32x2 lanes identical)
    const float h0 = hf[0], h1 = hf[1], h2 = hf[2], h3 = hf[3], h4 = hf[4], h5 = hf[5];
    const float g0 = gf[0], g1 = gf[1], g2 = gf[2], g3 = gf[3], g4 = gf[4], g5 = gf[5];
    const u64 H0 = pk(h0, h0), H1 = pk(h1, h1), H2 = pk(h2, h2);
    const u64 H3 = pk(h3, h3), H4 = pk(h4, h4), H5 = pk(h5, h5);
    const u64 G0 = pk(g0, g0), G1 = pk(g1, g1), G2 = pk(g2, g2);
    const u64 G3 = pk(g3, g3), G4 = pk(g4, g4), G5 = pk(g5, g5);

    // prime rolling window: rows reflH(r0-1), r0; prefetch row r0+1
    const int rm = reflH(r0 - 1);
    u64 s0 = ldg2(pss, rm), s1 = ldg2(pss, r0);
    u64 t0 = ldg2(psd, rm), t1 = ldg2(psd, r0);
    u64 u0 = ldg2(pds, rm), u1 = ldg2(pds, r0);
    u64 v0 = ldg2(pdd, rm), v1 = ldg2(pdd, r0);
    const int rp1 = reflH(r0 + 1);
    u64 pfs = ldg2(pss, rp1), pft = ldg2(psd, rp1);
    u64 pfu = ldg2(pds, rp1), pfv = ldg2(pdd, rp1);

    const bool eL = (tx == 0);
    const bool eR = (tx == NT - 1);

    int buf = 0;
    #pragma unroll 4
    for (int i = 0; i < ROWS; ++i) {
        const int r = r0 + i;
        const u64 s2 = pfs, t2 = pft, u2 = pfu, v2 = pfv;

        // prefetch row r+2 for next iteration
        const int rn = reflH(r + 2);
        pfs = ldg2(pss, rn); pft = ldg2(psd, rn);
        pfu = ldg2(pds, rn); pfv = ldg2(pdd, rn);

        // ---- column pass (both columns at once via f32x2) ----
        const u64 a0 = ffma2(H4, s0, ffma2(H2, s1, ffma2(H0, s2,
                       ffma2(G4, t0, ffma2(G2, t1, fmul2(G0, t2))))));   // sv0
        const u64 a1 = ffma2(H5, s0, ffma2(H3, s1, ffma2(H1, s2,
                       ffma2(G5, t0, ffma2(G3, t1, fmul2(G1, t2))))));   // sv1
        const u64 a2 = ffma2(H4, u0, ffma2(H2, u1, ffma2(H0, u2,
                       ffma2(G4, v0, ffma2(G2, v1, fmul2(G0, v2))))));   // dv0
        const u64 a3 = ffma2(H5, u0, ffma2(H3, u1, ffma2(H1, u2,
                       ffma2(G5, v0, ffma2(G3, v1, fmul2(G1, v2))))));   // dv1

        *(u64*)&sm[buf][0][2 + c] = a0;
        *(u64*)&sm[buf][1][2 + c] = a1;
        *(u64*)&sm[buf][2][2 + c] = a2;
        *(u64*)&sm[buf][3][2 + c] = a3;

        __syncthreads();

        // ---- row pass: shifted pairs per array ----
        u64 A[4], B[4], C[4];
        #pragma unroll
        for (int k = 0; k < 4; ++k) {
            const u64 mL = *(const u64*)&sm[buf][k][c];       // cols c-2, c-1
            const u64 mM = *(const u64*)&sm[buf][k][2 + c];   // cols c,   c+1
            const u64 mR = *(const u64*)&sm[buf][k][4 + c];   // cols c+2, c+3
            float l0, l1, m0, m1, q0, q1;
            unpk(mL, l0, l1); unpk(mM, m0, m1); unpk(mR, q0, q1);
            A[k] = pk(eL ? m1 : l1, m0);      // {v[c-1], v[c]}   (reflect at left)
            B[k] = mM;                        // {v[c],   v[c+1]}
            C[k] = pk(m1, eR ? m0 : q0);      // {v[c+1], v[c+2]} (reflect at right)
        }

        const u64 p00 = ffma2(H4, A[0], ffma2(H2, B[0], ffma2(H0, C[0],
                        ffma2(G4, A[2], ffma2(G2, B[2], fmul2(G0, C[2]))))));
        const u64 p01 = ffma2(H5, A[0], ffma2(H3, B[0], ffma2(H1, C[0],
                        ffma2(G5, A[2], ffma2(G3, B[2], fmul2(G1, C[2]))))));
        const u64 p10 = ffma2(H4, A[1], ffma2(H2, B[1], ffma2(H0, C[1],
                        ffma2(G4, A[3], ffma2(G2, B[3], fmul2(G0, C[3]))))));
        const u64 p11 = ffma2(H5, A[1], ffma2(H3, B[1], ffma2(H1, C[1],
                        ffma2(G5, A[3], ffma2(G3, B[3], fmul2(G1, C[3]))))));

        // interleave phases and store 16B per output row
        float e0, e1, f0, f1;
        unpk(p00, e0, e1); unpk(p01, f0, f1);
        *(float4*)(pout + (size_t)(2 * r) * (2 * WW)) = make_float4(e0, f0, e1, f1);
        unpk(p10, e0, e1); unpk(p11, f0, f1);
        *(float4*)(pout + (size_t)(2 * r + 1) * (2 * WW)) = make_float4(e0, f0, e1, f1);

        // roll vertical window
        s0 = s1; s1 = s2; t0 = t1; t1 = t2;
        u0 = u1; u1 = u2; v0 = v1; v1 = v2;
        buf ^= 1;
    }
}

extern "C" void kernel_launch(void* const* d_in, const int* in_sizes, int n_in,
                              void* d_out, int out_size) {
    const float* ss = (const float*)d_in[0];
    const float* sd = (const float*)d_in[1];
    const float* ds = (const float*)d_in[2];
    const float* dd = (const float*)d_in[3];
    const float* h  = (const float*)d_in[4];
    const float* g  = (const float*)d_in[5];
    float* out = (float*)d_out;

    dim3 grid(1, HH / ROWS, 4 * 64);   // (1, 8, 256)
    idwt2d<<<grid, NT>>>(ss, sd, ds, dd, h, g, out);
}